// round 12
// baseline (speedup 1.0000x reference)
#include <cuda_runtime.h>
#include <cstdint>

#define LOG2E_F 1.44269504088896340736f

constexpr int Bz = 2, SQ = 2048, SKV = 2048, HQ = 16, HKV = 4, DH = 128;
constexpr int BR = 64, BC = 32, NT = 128;
constexpr int NTILE = SKV / BC;              // 64 kv tiles per (b,hk)

// smem float strides/offsets (double-buffered K and V^T)
constexpr int QSTR = 136, KSTR = 136, VTSTR = 40;
constexpr int F_Q  = 0;                      // 64*136 = 8704
constexpr int F_K0 = 8704;                   // 32*136 = 4352 per buf
constexpr int F_K1 = F_K0 + BC * KSTR;       // 13056
constexpr int F_V0 = F_K1 + BC * KSTR;       // 17408 ; 128*40 = 5120 per buf
constexpr int F_V1 = F_V0 + DH * VTSTR;      // 22528
constexpr int F_TOT = F_V1 + DH * VTSTR;     // 27648 floats
constexpr size_t SMEM_BYTES = (size_t)F_TOT * 4;   // 110592 B -> 2 CTAs/SM

// packed K: [b][hk][tile32][kv(32)][136] tf32, k-pair interleaved (A/B frag)
__device__ float g_kc[(size_t)Bz * HKV * NTILE * BC * KSTR];
// packed V^T: [b][hk][tile32][d(128)][40] tf32, kv plain order
__device__ float g_vtc[(size_t)Bz * HKV * NTILE * DH * VTSTR];

// ---------------- helpers ----------------
__device__ __forceinline__ float tf32r(float x) {
    unsigned u;
    asm("cvt.rna.tf32.f32 %0, %1;" : "=r"(u) : "f"(x));
    return __uint_as_float(u);
}
__device__ __forceinline__ float ex2f(float x) {
    float y;
    asm("ex2.approx.f32 %0, %1;" : "=f"(y) : "f"(x));
    return y;
}
__device__ __forceinline__ uint32_t smem_u32(const void* p) {
    uint32_t a;
    asm("{ .reg .u64 t; cvta.to.shared.u64 t, %1; cvt.u32.u64 %0, t; }"
        : "=r"(a) : "l"(p));
    return a;
}
__device__ __forceinline__ void cpa16(uint32_t dst, const float* src) {
    asm volatile("cp.async.cg.shared.global [%0], [%1], 16;"
                 :: "r"(dst), "l"(src));
}
__device__ __forceinline__ void cpa_commit() {
    asm volatile("cp.async.commit_group;" ::: "memory");
}
__device__ __forceinline__ void cpa_wait0() {
    asm volatile("cp.async.wait_group 0;" ::: "memory");
}
// m16n8k8 row.col tf32 mma.  a0=aL.x a1=aH.x a2=aL.y a3=aH.y
__device__ __forceinline__ void mma8(float* c, float2 aL, float2 aH, float2 b) {
    unsigned a0 = __float_as_uint(aL.x), a1 = __float_as_uint(aH.x);
    unsigned a2 = __float_as_uint(aL.y), a3 = __float_as_uint(aH.y);
    unsigned b0 = __float_as_uint(b.x),  b1 = __float_as_uint(b.y);
    asm volatile(
        "mma.sync.aligned.m16n8k8.row.col.f32.tf32.tf32.f32 "
        "{%0,%1,%2,%3}, {%4,%5,%6,%7}, {%8,%9}, {%0,%1,%2,%3};\n"
        : "+f"(c[0]), "+f"(c[1]), "+f"(c[2]), "+f"(c[3])
        : "r"(a0), "r"(a1), "r"(a2), "r"(a3), "r"(b0), "r"(b1));
}

// ---------------- prepass: K pack (fragment k-pair interleave) -------------
__global__ void kprep_kernel(const float* __restrict__ k) {
    int idx = blockIdx.x * 256 + threadIdx.x;     // one float4 each
    int d  = (idx & 31) * 4;
    int t  = idx >> 5;
    int hk = t & 3;  t >>= 2;
    int s  = t & (SKV - 1);
    int b  = t >> 11;
    float4 v4 = *(const float4*)(k + (((size_t)b * SKV + s) * HKV + hk) * DH + d);
    float* dst = g_kc + (((size_t)(b * HKV + hk) * NTILE + (s >> 5)) * BC
                         + (s & 31)) * KSTR;
    int g = (d & ~7) + ((d & 4) ? 1 : 0);
    dst[g + 0] = tf32r(v4.x);
    dst[g + 2] = tf32r(v4.y);
    dst[g + 4] = tf32r(v4.z);
    dst[g + 6] = tf32r(v4.w);
}

// ---------------- prepass: V transpose+pack (plain kv order) ---------------
__global__ void vtprep_kernel(const float* __restrict__ v) {
    __shared__ float t[32][33];
    const int kvt = blockIdx.x;          // kv tile (32 wide)
    const int d0  = blockIdx.y * 32;
    const int bh  = blockIdx.z;          // b*HKV+hk
    const int b = bh >> 2, hk = bh & 3;
    const int tx = threadIdx.x, ty = threadIdx.y;   // 32 x 8
    const float* src = v + ((size_t)b * SKV * HKV + hk) * DH + d0;
    #pragma unroll
    for (int i = 0; i < 4; ++i) {
        int kvl = ty + 8 * i;
        t[kvl][tx] = src[(size_t)(kvt * BC + kvl) * (HKV * DH) + tx];
    }
    __syncthreads();
    float* dst = g_vtc + ((size_t)bh * NTILE + kvt) * (DH * VTSTR)
               + (size_t)d0 * VTSTR;
    #pragma unroll
    for (int i = 0; i < 4; ++i) {
        int e = i * 256 + ty * 32 + tx;      // 1024 elements (32d x 32kv)
        int dl = e >> 5, kvl = e & 31;
        dst[dl * VTSTR + kvl] = tf32r(t[kvl][dl]);
    }
}

// ---------------- main attention kernel ----------------
__global__ void __launch_bounds__(NT, 2)
fa_kernel(const float* __restrict__ q,
          const float* __restrict__ mask,
          float* __restrict__ out)
{
    extern __shared__ float sm[];
    const uint32_t sb = smem_u32(sm);

    const int tid = threadIdx.x;
    const int w = tid >> 5;            // 4 warps, warp owns rows w*16..w*16+15
    const int lane = tid & 31;
    const int qgrp = lane >> 2;
    const int qid  = lane & 3;

    const int bx = blockIdx.x;
    const int q0 = bx * BR;
    const int h  = blockIdx.y;
    const int b  = blockIdx.z;
    const int hk = h & (HKV - 1);
    const int bh = b * HKV + hk;
    const int ntiles = (q0 + BR) / BC;   // 2bx+2

    const uint32_t KB[2] = { sb + F_K0 * 4u, sb + F_K1 * 4u };
    const uint32_t VB[2] = { sb + F_V0 * 4u, sb + F_V1 * 4u };
    const float* kc0 = g_kc + (size_t)bh * NTILE * (BC * KSTR);
    const float* vc0 = g_vtc + (size_t)bh * NTILE * (DH * VTSTR);

    // ---- prologue: prefetch tile 0 into buffer 0 ----
    {
        #pragma unroll
        for (int i = 0; i < 10; ++i) {
            int idx = tid + NT * i;
            if (idx < BC * KSTR / 4)  cpa16(KB[0] + idx * 16, kc0 + idx * 4);
            if (idx < DH * VTSTR / 4) cpa16(VB[0] + idx * 16, vc0 + idx * 4);
        }
        cpa_commit();
    }

    // ---- Q tile: LDG + scale + tf32 + pair-interleaved STS ----
    {
        const float qscale = LOG2E_F * 0.08838834764831845f;  // log2e/sqrt(128)
        const float* qb = q + (((size_t)b * SQ + q0) * HQ + h) * DH;
        #pragma unroll
        for (int i = 0; i < 16; ++i) {
            int f4 = tid + NT * i;
            int row = f4 >> 5;
            int c = (f4 & 31) << 2;
            float4 v4 = *(const float4*)(qb + (size_t)row * (HQ * DH) + c);
            int g = (c & ~7) + ((c & 4) ? 1 : 0);
            float* dst = sm + F_Q + row * QSTR;
            dst[g + 0] = tf32r(v4.x * qscale);
            dst[g + 2] = tf32r(v4.y * qscale);
            dst[g + 4] = tf32r(v4.z * qscale);
            dst[g + 6] = tf32r(v4.w * qscale);
        }
    }

    const int rg0 = q0 + w * 16 + qgrp;      // global row (and rg0+8)
    const int rwmax = q0 + w * 16 + 15;      // causal warp bound
    const float* mrow0 = mask + ((size_t)(b * HQ + h) * SQ + rg0) * SKV;
    const float* mrow1 = mrow0 + (size_t)8 * SKV;
    const float* qrow0 = sm + F_Q + (w * 16 + qgrp) * QSTR;
    const float* qrow1 = qrow0 + 8 * QSTR;

    float O[16][4];
    #pragma unroll
    for (int nt = 0; nt < 16; ++nt) {
        O[nt][0] = 0.f; O[nt][1] = 0.f; O[nt][2] = 0.f; O[nt][3] = 0.f;
    }
    float ls0 = 0.f, ls1 = 0.f;

    for (int j = 0; j < ntiles; ++j) {
        const int kv0 = j * BC;
        const int cur = j & 1, nxt = cur ^ 1;

        cpa_wait0();                    // tile j resident (sole group in flight)
        __syncthreads();                // publish tile j; iter j-1 reads done

        // ---- prefetch tile j+1 into `nxt` (completes during this compute) --
        if (j + 1 < ntiles) {
            const float* ks = kc0 + (size_t)(j + 1) * (BC * KSTR);
            const float* vs = vc0 + (size_t)(j + 1) * (DH * VTSTR);
            #pragma unroll
            for (int i = 0; i < 10; ++i) {
                int idx = tid + NT * i;
                if (idx < BC * KSTR / 4)  cpa16(KB[nxt] + idx * 16, ks + idx * 4);
                if (idx < DH * VTSTR / 4) cpa16(VB[nxt] + idx * 16, vs + idx * 4);
            }
        }
        cpa_commit();                   // commit (possibly empty) group

        if (kv0 <= rwmax) {
            // ---- mask prefetch into registers (hidden under MMA1) ----
            float2 mk0[4], mk1[4];
            #pragma unroll
            for (int nt = 0; nt < 4; ++nt) {
                mk0[nt] = *(const float2*)(mrow0 + kv0 + nt * 8 + 2 * qid);
                mk1[nt] = *(const float2*)(mrow1 + kv0 + nt * 8 + 2 * qid);
            }

            // ---- MMA1: S(m16 x n32) = Q @ K^T ----
            float S[4][4];
            #pragma unroll
            for (int nt = 0; nt < 4; ++nt) {
                S[nt][0] = 0.f; S[nt][1] = 0.f; S[nt][2] = 0.f; S[nt][3] = 0.f;
            }
            {
                const float* Ks = sm + (cur ? F_K1 : F_K0);
                #pragma unroll
                for (int kt = 0; kt < 16; ++kt) {
                    const int ko = kt * 8 + 2 * qid;
                    float2 aL = *(const float2*)(qrow0 + ko);
                    float2 aH = *(const float2*)(qrow1 + ko);
                    #pragma unroll
                    for (int nt = 0; nt < 4; ++nt) {
                        float2 bb = *(const float2*)(Ks + (nt * 8 + qgrp) * KSTR + ko);
                        mma8(S[nt], aL, aH, bb);
                    }
                }
            }

            // ---- softmax: P = exp2(S + mask*log2e), causal-zeroed, in regs --
            #pragma unroll
            for (int nt = 0; nt < 4; ++nt) {
                const int c0 = kv0 + nt * 8 + 2 * qid;
                float p00 = (c0     <= rg0)     ? ex2f(S[nt][0] + LOG2E_F * mk0[nt].x) : 0.f;
                float p01 = (c0 + 1 <= rg0)     ? ex2f(S[nt][1] + LOG2E_F * mk0[nt].y) : 0.f;
                float p10 = (c0     <= rg0 + 8) ? ex2f(S[nt][2] + LOG2E_F * mk1[nt].x) : 0.f;
                float p11 = (c0 + 1 <= rg0 + 8) ? ex2f(S[nt][3] + LOG2E_F * mk1[nt].y) : 0.f;
                ls0 += p00 + p01;
                ls1 += p10 + p11;
                S[nt][0] = tf32r(p00);
                S[nt][1] = tf32r(p01);
                S[nt][2] = tf32r(p10);
                S[nt][3] = tf32r(p11);
            }

            // ---- MMA2: O(m16 x d128) += P @ V, P straight from registers ----
            {
                const float* Vs = sm + (cur ? F_V1 : F_V0);
                #pragma unroll
                for (int kt = 0; kt < 4; ++kt) {
                    float2 aL = make_float2(S[kt][0], S[kt][1]);
                    float2 aH = make_float2(S[kt][2], S[kt][3]);
                    #pragma unroll
                    for (int nt = 0; nt < 16; ++nt) {
                        float2 bb = *(const float2*)(Vs + (nt * 8 + qgrp) * VTSTR
                                                     + kt * 8 + 2 * qid);
                        mma8(O[nt], aL, aH, bb);
                    }
                }
            }
        }
    }

    // ---- row sums (reduce over qid lanes), normalize, store ----
    ls0 += __shfl_xor_sync(0xffffffffu, ls0, 1);
    ls0 += __shfl_xor_sync(0xffffffffu, ls0, 2);
    ls1 += __shfl_xor_sync(0xffffffffu, ls1, 1);
    ls1 += __shfl_xor_sync(0xffffffffu, ls1, 2);
    const float inv0 = 1.0f / ls0;
    const float inv1 = 1.0f / ls1;

    float* o0 = out + (((size_t)b * SQ + rg0) * HQ + h) * DH;
    float* o1 = o0 + (size_t)8 * HQ * DH;
    #pragma unroll
    for (int nt = 0; nt < 16; ++nt) {
        const int c = nt * 8 + 2 * qid;
        *(float2*)(o0 + c) = make_float2(O[nt][0] * inv0, O[nt][1] * inv0);
        *(float2*)(o1 + c) = make_float2(O[nt][2] * inv1, O[nt][3] * inv1);
    }
}

extern "C" void kernel_launch(void* const* d_in, const int* in_sizes, int n_in,
                              void* d_out, int out_size) {
    (void)in_sizes; (void)n_in; (void)out_size;
    const float* q = (const float*)d_in[0];
    const float* k = (const float*)d_in[1];
    const float* v = (const float*)d_in[2];
    const float* mask = (const float*)d_in[3];
    float* out = (float*)d_out;

    cudaFuncSetAttribute(fa_kernel,
                         cudaFuncAttributeMaxDynamicSharedMemorySize,
                         (int)SMEM_BYTES);

    kprep_kernel<<<(Bz * SKV * HKV * DH / 4) / 256, 256>>>(k);
    vtprep_kernel<<<dim3(NTILE, DH / 32, Bz * HKV), dim3(32, 8)>>>(v);
    fa_kernel<<<dim3(SQ / BR, HQ, Bz), NT, SMEM_BYTES>>>(q, mask, out);
}

// round 14
// speedup vs baseline: 1.4411x; 1.4411x over previous
#include <cuda_runtime.h>
#include <cstdint>

#define LOG2E_F 1.44269504088896340736f

constexpr int Bz = 2, SQ = 2048, SKV = 2048, HQ = 16, HKV = 4, DH = 128;
constexpr int BR = 64, BC = 64, NT = 128;
constexpr int NTILE = SKV / BC;              // 32 kv tiles per (b,hk)

// smem float strides/offsets (single K buffer + single V buffer)
constexpr int KSTR = 136, VTSTR = 72;
constexpr int F_K = 0;                       // 64*136 = 8704 floats
constexpr int F_V = 8704;                    // 128*72 = 9216 floats
constexpr int F_TOT = F_V + DH * VTSTR;      // 17920 floats
constexpr size_t SMEM_BYTES = (size_t)F_TOT * 4;   // 71680 B -> 2 CTAs/SM

// packed K: [b][hk][tile64][kv(64)][136] tf32, k-pair interleaved (A/B frag)
__device__ float g_kc[(size_t)Bz * HKV * NTILE * BC * KSTR];
// packed V^T: [b][hk][tile64][d(128)][72] tf32, kv plain order
__device__ float g_vtc[(size_t)Bz * HKV * NTILE * DH * VTSTR];

// ---------------- helpers ----------------
__device__ __forceinline__ float tf32r(float x) {
    unsigned u;
    asm("cvt.rna.tf32.f32 %0, %1;" : "=r"(u) : "f"(x));
    return __uint_as_float(u);
}
__device__ __forceinline__ float ex2f(float x) {
    float y;
    asm("ex2.approx.f32 %0, %1;" : "=f"(y) : "f"(x));
    return y;
}
__device__ __forceinline__ uint32_t smem_u32(const void* p) {
    uint32_t a;
    asm("{ .reg .u64 t; cvta.to.shared.u64 t, %1; cvt.u32.u64 %0, t; }"
        : "=r"(a) : "l"(p));
    return a;
}
__device__ __forceinline__ void cpa16(uint32_t dst, const float* src) {
    asm volatile("cp.async.cg.shared.global [%0], [%1], 16;"
                 :: "r"(dst), "l"(src));
}
__device__ __forceinline__ void cpa_commit() {
    asm volatile("cp.async.commit_group;" ::: "memory");
}
__device__ __forceinline__ void cpa_wait0() {
    asm volatile("cp.async.wait_group 0;" ::: "memory");
}
__device__ __forceinline__ void cpa_wait1() {
    asm volatile("cp.async.wait_group 1;" ::: "memory");
}
// m16n8k8 row.col tf32 mma.  a0=aL.x a1=aH.x a2=aL.y a3=aH.y
__device__ __forceinline__ void mma8(float* c, float2 aL, float2 aH, float2 b) {
    unsigned a0 = __float_as_uint(aL.x), a1 = __float_as_uint(aH.x);
    unsigned a2 = __float_as_uint(aL.y), a3 = __float_as_uint(aH.y);
    unsigned b0 = __float_as_uint(b.x),  b1 = __float_as_uint(b.y);
    asm volatile(
        "mma.sync.aligned.m16n8k8.row.col.f32.tf32.tf32.f32 "
        "{%0,%1,%2,%3}, {%4,%5,%6,%7}, {%8,%9}, {%0,%1,%2,%3};\n"
        : "+f"(c[0]), "+f"(c[1]), "+f"(c[2]), "+f"(c[3])
        : "r"(a0), "r"(a1), "r"(a2), "r"(a3), "r"(b0), "r"(b1));
}

// ---------------- prepass: K pack (fragment k-pair interleave) -------------
__global__ void kprep_kernel(const float* __restrict__ k) {
    int idx = blockIdx.x * 256 + threadIdx.x;     // one float4 each
    int d  = (idx & 31) * 4;
    int t  = idx >> 5;
    int hk = t & 3;  t >>= 2;
    int s  = t & (SKV - 1);
    int b  = t >> 11;
    float4 v4 = *(const float4*)(k + (((size_t)b * SKV + s) * HKV + hk) * DH + d);
    float* dst = g_kc + (((size_t)(b * HKV + hk) * NTILE + (s >> 6)) * BC
                         + (s & 63)) * KSTR;
    int g = (d & ~7) + ((d & 4) ? 1 : 0);
    dst[g + 0] = tf32r(v4.x);
    dst[g + 2] = tf32r(v4.y);
    dst[g + 4] = tf32r(v4.z);
    dst[g + 6] = tf32r(v4.w);
}

// ---------------- prepass: V transpose+pack (plain kv order) ---------------
__global__ void vtprep_kernel(const float* __restrict__ v) {
    __shared__ float t[64][33];
    const int kvt = blockIdx.x;          // kv tile (64 wide)
    const int d0  = blockIdx.y * 32;
    const int bh  = blockIdx.z;          // b*HKV+hk
    const int b = bh >> 2, hk = bh & 3;
    const int tx = threadIdx.x, ty = threadIdx.y;   // 32 x 8
    const float* src = v + ((size_t)b * SKV * HKV + hk) * DH + d0;
    #pragma unroll
    for (int i = 0; i < 8; ++i) {
        int kvl = ty + 8 * i;
        t[kvl][tx] = src[(size_t)(kvt * 64 + kvl) * (HKV * DH) + tx];
    }
    __syncthreads();
    float* dst = g_vtc + ((size_t)bh * NTILE + kvt) * (DH * VTSTR)
               + (size_t)d0 * VTSTR;
    #pragma unroll
    for (int i = 0; i < 8; ++i) {
        int e = i * 256 + ty * 32 + tx;
        int dl = e >> 6, kvl = e & 63;
        dst[dl * VTSTR + kvl] = tf32r(t[kvl][dl]);
    }
}

// ---------------- main attention kernel ----------------
__global__ void __launch_bounds__(NT, 2)
fa_kernel(const float* __restrict__ q,
          const float* __restrict__ mask,
          float* __restrict__ out)
{
    extern __shared__ float sm[];
    const uint32_t sb = smem_u32(sm);

    const int tid = threadIdx.x;
    const int w = tid >> 5;            // 4 warps, warp owns rows w*16..w*16+15
    const int lane = tid & 31;
    const int qgrp = lane >> 2;
    const int qid  = lane & 3;

    const int bx = blockIdx.x;
    const int q0 = bx * BR;
    const int h  = blockIdx.y;
    const int b  = blockIdx.z;
    const int hk = h & (HKV - 1);
    const int bh = b * HKV + hk;
    const int ntiles = bx + 1;

    const uint32_t KBuf = sb + F_K * 4u;
    const uint32_t VBuf = sb + F_V * 4u;
    const float* kc0 = g_kc + (size_t)bh * NTILE * (BC * KSTR);
    const float* vc0 = g_vtc + (size_t)bh * NTILE * (DH * VTSTR);

    // ---- prologue: issue K_0 (group) ----
    #pragma unroll
    for (int i = 0; i < 17; ++i) {
        int idx = tid + NT * i;
        if (idx < BC * KSTR / 4) cpa16(KBuf + idx * 16, kc0 + idx * 4);
    }
    cpa_commit();

    const int rg0 = q0 + w * 16 + qgrp;      // global row (and rg0+8)
    // ---- Q fragments into registers, INTERLEAVE-MATCHED to K smem layout --
    // K smem slot kt*8+2*qid holds logical k = kt*8+qid; slot +1 holds k+4.
    // So A slot pair must be (q[kt*8+qid], q[kt*8+qid+4]).
    float2 qA0[16], qA1[16];
    {
        const float qscale = LOG2E_F * 0.08838834764831845f;  // log2e/sqrt(128)
        const float* qb0 = q + (((size_t)b * SQ + rg0) * HQ + h) * DH;
        const float* qb1 = qb0 + (size_t)8 * HQ * DH;
        #pragma unroll
        for (int kt = 0; kt < 16; ++kt) {
            float a00 = qb0[kt * 8 + qid];
            float a01 = qb0[kt * 8 + qid + 4];
            float a10 = qb1[kt * 8 + qid];
            float a11 = qb1[kt * 8 + qid + 4];
            qA0[kt] = make_float2(tf32r(a00 * qscale), tf32r(a01 * qscale));
            qA1[kt] = make_float2(tf32r(a10 * qscale), tf32r(a11 * qscale));
        }
    }

    const float* mrow0 = mask + ((size_t)(b * HQ + h) * SQ + rg0) * SKV;
    const float* mrow1 = mrow0 + (size_t)8 * SKV;

    float O[16][4];
    #pragma unroll
    for (int nt = 0; nt < 16; ++nt) {
        O[nt][0] = 0.f; O[nt][1] = 0.f; O[nt][2] = 0.f; O[nt][3] = 0.f;
    }
    float ls0 = 0.f, ls1 = 0.f;

    for (int j = 0; j < ntiles; ++j) {
        const int kv0 = j * BC;

        cpa_wait0();                 // K_j resident (only pending group)
        __syncthreads();             // publish K_j; proves MMA2_{j-1} done (V free)

        // ---- issue V_j (hidden under MMA1 + softmax) ----
        {
            const float* vs = vc0 + (size_t)j * (DH * VTSTR);
            #pragma unroll
            for (int i = 0; i < 18; ++i) {
                int idx = tid + NT * i;
                if (idx < DH * VTSTR / 4) cpa16(VBuf + idx * 16, vs + idx * 4);
            }
        }
        cpa_commit();                // group: V_j

        // ---- mask prefetch into registers (hidden under MMA1) ----
        float2 mk0[8], mk1[8];
        #pragma unroll
        for (int nt = 0; nt < 8; ++nt) {
            mk0[nt] = *(const float2*)(mrow0 + kv0 + nt * 8 + 2 * qid);
            mk1[nt] = *(const float2*)(mrow1 + kv0 + nt * 8 + 2 * qid);
        }

        // ---- MMA1: S(m16 x n64) = Q @ K^T, Q from registers ----
        float S[8][4];
        #pragma unroll
        for (int nt = 0; nt < 8; ++nt) {
            S[nt][0] = 0.f; S[nt][1] = 0.f; S[nt][2] = 0.f; S[nt][3] = 0.f;
        }
        {
            const float* Ks = sm + F_K;
            #pragma unroll
            for (int kt = 0; kt < 16; ++kt) {
                const int ko = kt * 8 + 2 * qid;
                #pragma unroll
                for (int nt = 0; nt < 8; ++nt) {
                    float2 bb = *(const float2*)(Ks + (nt * 8 + qgrp) * KSTR + ko);
                    mma8(S[nt], qA0[kt], qA1[kt], bb);
                }
            }
        }
        __syncthreads();             // all K_j reads done -> K buffer free

        // ---- issue K_{j+1} (hidden under softmax + MMA2) ----
        if (j + 1 < ntiles) {
            const float* ks = kc0 + (size_t)(j + 1) * (BC * KSTR);
            #pragma unroll
            for (int i = 0; i < 17; ++i) {
                int idx = tid + NT * i;
                if (idx < BC * KSTR / 4) cpa16(KBuf + idx * 16, ks + idx * 4);
            }
        }
        cpa_commit();                // group: K_{j+1} (possibly empty)

        // ---- softmax: P = exp2(S + mask*log2e), causal-zeroed, in regs ----
        #pragma unroll
        for (int nt = 0; nt < 8; ++nt) {
            const int c0 = kv0 + nt * 8 + 2 * qid;
            float p00 = (c0     <= rg0)     ? ex2f(S[nt][0] + LOG2E_F * mk0[nt].x) : 0.f;
            float p01 = (c0 + 1 <= rg0)     ? ex2f(S[nt][1] + LOG2E_F * mk0[nt].y) : 0.f;
            float p10 = (c0     <= rg0 + 8) ? ex2f(S[nt][2] + LOG2E_F * mk1[nt].x) : 0.f;
            float p11 = (c0 + 1 <= rg0 + 8) ? ex2f(S[nt][3] + LOG2E_F * mk1[nt].y) : 0.f;
            ls0 += p00 + p01;
            ls1 += p10 + p11;
            S[nt][0] = tf32r(p00);
            S[nt][1] = tf32r(p01);
            S[nt][2] = tf32r(p10);
            S[nt][3] = tf32r(p11);
        }

        cpa_wait1();                 // V_j done (K_{j+1} may still be pending)
        __syncthreads();             // publish V_j

        // ---- MMA2: O(m16 x d128) += P @ V, P straight from registers ----
        {
            const float* Vs = sm + F_V;
            #pragma unroll
            for (int kt = 0; kt < 8; ++kt) {
                float2 aL = make_float2(S[kt][0], S[kt][1]);
                float2 aH = make_float2(S[kt][2], S[kt][3]);
                #pragma unroll
                for (int nt = 0; nt < 16; ++nt) {
                    float2 bb = *(const float2*)(Vs + (nt * 8 + qgrp) * VTSTR
                                                 + kt * 8 + 2 * qid);
                    mma8(O[nt], aL, aH, bb);
                }
            }
        }
    }

    // ---- row sums (reduce over qid lanes), normalize, store ----
    ls0 += __shfl_xor_sync(0xffffffffu, ls0, 1);
    ls0 += __shfl_xor_sync(0xffffffffu, ls0, 2);
    ls1 += __shfl_xor_sync(0xffffffffu, ls1, 1);
    ls1 += __shfl_xor_sync(0xffffffffu, ls1, 2);
    const float inv0 = 1.0f / ls0;
    const float inv1 = 1.0f / ls1;

    float* o0 = out + (((size_t)b * SQ + rg0) * HQ + h) * DH;
    float* o1 = o0 + (size_t)8 * HQ * DH;
    #pragma unroll
    for (int nt = 0; nt < 16; ++nt) {
        const int c = nt * 8 + 2 * qid;
        *(float2*)(o0 + c) = make_float2(O[nt][0] * inv0, O[nt][1] * inv0);
        *(float2*)(o1 + c) = make_float2(O[nt][2] * inv1, O[nt][3] * inv1);
    }
}

extern "C" void kernel_launch(void* const* d_in, const int* in_sizes, int n_in,
                              void* d_out, int out_size) {
    (void)in_sizes; (void)n_in; (void)out_size;
    const float* q = (const float*)d_in[0];
    const float* k = (const float*)d_in[1];
    const float* v = (const float*)d_in[2];
    const float* mask = (const float*)d_in[3];
    float* out = (float*)d_out;

    cudaFuncSetAttribute(fa_kernel,
                         cudaFuncAttributeMaxDynamicSharedMemorySize,
                         (int)SMEM_BYTES);

    kprep_kernel<<<(Bz * SKV * HKV * DH / 4) / 256, 256>>>(k);
    vtprep_kernel<<<dim3(NTILE, DH / 32, Bz * HKV), dim3(32, 8)>>>(v);
    fa_kernel<<<dim3(SQ / BR, HQ, Bz), NT, SMEM_BYTES>>>(q, mask, out);
}

// round 15
// speedup vs baseline: 1.5673x; 1.0876x over previous
#include <cuda_runtime.h>
#include <cuda_fp16.h>
#include <cstdint>

#define LOG2E_F 1.44269504088896340736f

constexpr int Bz = 2, SQ = 2048, SKV = 2048, HQ = 16, HKV = 4, DH = 128;
constexpr int BR = 64, BC = 64, NT = 128;
constexpr int NTILE = SKV / BC;              // 32 kv tiles per (b,hk)

// fp16 smem strides (in half units)
constexpr int KSTR_H  = 144;   // K row: 128 halves data + pad (72 words mod 32 = 8: conflict-free)
constexpr int VTSTR_H = 80;    // V^T row: 64 halves data + pad (40 words mod 32 = 8)
constexpr int K_TILE_BYTES = BC * KSTR_H * 2;     // 18432
constexpr int V_TILE_BYTES = DH * VTSTR_H * 2;    // 20480
constexpr size_t SMEM_BYTES = K_TILE_BYTES + V_TILE_BYTES;  // 38912 -> 2+ CTAs/SM

// packed K: [b][hk][tile64][kv(64)][144h] fp16, vperm16 interleave on dh
__device__ __half2 g_kc[(size_t)Bz * HKV * NTILE * BC * (KSTR_H / 2)];
// packed V^T: [b][hk][tile64][d(128)][80h] fp16, vperm16 interleave on kv
__device__ __half g_vtc[(size_t)Bz * HKV * NTILE * DH * VTSTR_H];

// ---------------- helpers ----------------
__device__ __forceinline__ float ex2f(float x) {
    float y;
    asm("ex2.approx.f32 %0, %1;" : "=f"(y) : "f"(x));
    return y;
}
__device__ __forceinline__ uint32_t smem_u32(const void* p) {
    uint32_t a;
    asm("{ .reg .u64 t; cvta.to.shared.u64 t, %1; cvt.u32.u64 %0, t; }"
        : "=r"(a) : "l"(p));
    return a;
}
__device__ __forceinline__ void cpa16(uint32_t dst, const void* src) {
    asm volatile("cp.async.cg.shared.global [%0], [%1], 16;"
                 :: "r"(dst), "l"(src));
}
__device__ __forceinline__ void cpa_commit() {
    asm volatile("cp.async.commit_group;" ::: "memory");
}
__device__ __forceinline__ void cpa_wait0() {
    asm volatile("cp.async.wait_group 0;" ::: "memory");
}
__device__ __forceinline__ void cpa_wait1() {
    asm volatile("cp.async.wait_group 1;" ::: "memory");
}
__device__ __forceinline__ uint32_t packh2(float lo, float hi) {
    __half2 h = __floats2half2_rn(lo, hi);   // x=lo (low 16 bits), y=hi
    return *reinterpret_cast<uint32_t*>(&h);
}
// m16n8k16 row.col fp16 mma, fp32 accumulate
__device__ __forceinline__ void mma16(float* c, const uint32_t* a, uint2 b) {
    asm volatile(
        "mma.sync.aligned.m16n8k16.row.col.f32.f16.f16.f32 "
        "{%0,%1,%2,%3}, {%4,%5,%6,%7}, {%8,%9}, {%0,%1,%2,%3};\n"
        : "+f"(c[0]), "+f"(c[1]), "+f"(c[2]), "+f"(c[3])
        : "r"(a[0]), "r"(a[1]), "r"(a[2]), "r"(a[3]), "r"(b.x), "r"(b.y));
}
// 16-block interleave: pos(k) within 16-block = 4*((k>>1)&3) + (k&1) + 2*((k>>3)&1)
// -> B-fragment {k=2q, 2q+1, 2q+8, 2q+9} is one aligned LDS.64 at half-offset 4q
__device__ __forceinline__ int vperm16(int k) {
    return (k & ~15) + 4 * ((k >> 1) & 3) + (k & 1) + 2 * ((k >> 3) & 1);
}

// ---------------- prepass: K pack (fp16, vperm16 on dh) --------------------
__global__ void kprep_kernel(const float* __restrict__ k) {
    int idx = blockIdx.x * 256 + threadIdx.x;     // one float4 each
    int d  = (idx & 31) * 4;
    int t  = idx >> 5;
    int hk = t & 3;  t >>= 2;
    int s  = t & (SKV - 1);
    int b  = t >> 11;
    float4 v4 = *(const float4*)(k + (((size_t)b * SKV + s) * HKV + hk) * DH + d);
    __half2* dst = g_kc + (((size_t)(b * HKV + hk) * NTILE + (s >> 6)) * BC
                           + (s & 63)) * (KSTR_H / 2) + (d & ~15) / 2;
    // h2 slots for (d..d+3) by (d>>2)&3:  {0,2} {4,6} {1,3} {5,7}
    const int c = (d >> 2) & 3;
    const int t0 = (c & 1) ? ((c >> 1) ? 5 : 1) : ((c >> 1) ? 4 : 0);
    // c=0 -> 0,2 ; c=1 -> 4,6 ; c=2 -> 1,3 ; c=3 -> 5,7
    int a0 = (c == 0) ? 0 : (c == 1) ? 4 : (c == 2) ? 1 : 5;
    (void)t0;
    dst[a0]     = __floats2half2_rn(v4.x, v4.y);
    dst[a0 + 2] = __floats2half2_rn(v4.z, v4.w);
}

// ---------------- prepass: V transpose+pack (fp16, vperm16 on kv) ----------
__global__ void vtprep_kernel(const float* __restrict__ v) {
    __shared__ float t[64][33];
    const int kvt = blockIdx.x;          // kv tile (64 wide)
    const int d0  = blockIdx.y * 32;
    const int bh  = blockIdx.z;          // b*HKV+hk
    const int b = bh >> 2, hk = bh & 3;
    const int tx = threadIdx.x, ty = threadIdx.y;   // 32 x 8
    const float* src = v + ((size_t)b * SKV * HKV + hk) * DH + d0;
    #pragma unroll
    for (int i = 0; i < 8; ++i) {
        int kvl = ty + 8 * i;
        t[kvl][tx] = src[(size_t)(kvt * 64 + kvl) * (HKV * DH) + tx];
    }
    __syncthreads();
    __half* dst = g_vtc + ((size_t)bh * NTILE + kvt) * (DH * VTSTR_H)
                + (size_t)d0 * VTSTR_H;
    #pragma unroll
    for (int i = 0; i < 8; ++i) {
        int e = i * 256 + ty * 32 + tx;
        int dl = e >> 6, kvl = e & 63;
        dst[dl * VTSTR_H + vperm16(kvl)] = __float2half_rn(t[kvl][dl]);
    }
}

// ---------------- main attention kernel ----------------
__global__ void __launch_bounds__(NT, 2)
fa_kernel(const float* __restrict__ q,
          const float* __restrict__ mask,
          float* __restrict__ out)
{
    extern __shared__ char sma[];
    __half* Ks = (__half*)sma;
    __half* Vs = (__half*)(sma + K_TILE_BYTES);
    const uint32_t KBuf = smem_u32(Ks);
    const uint32_t VBuf = smem_u32(Vs);

    const int tid = threadIdx.x;
    const int w = tid >> 5;            // 4 warps, warp owns rows w*16..w*16+15
    const int lane = tid & 31;
    const int qgrp = lane >> 2;
    const int qid  = lane & 3;

    const int bx = blockIdx.x;
    const int q0 = bx * BR;
    const int h  = blockIdx.y;
    const int b  = blockIdx.z;
    const int hk = h & (HKV - 1);
    const int bh = b * HKV + hk;
    const int ntiles = bx + 1;

    const __half2* kc0 = g_kc + (size_t)bh * NTILE * (BC * (KSTR_H / 2));
    const __half*  vc0 = g_vtc + (size_t)bh * NTILE * (DH * VTSTR_H);

    // ---- prologue: issue K_0 (group) ----
    #pragma unroll
    for (int i = 0; i < 9; ++i) {
        int idx = tid + NT * i;
        if (idx < K_TILE_BYTES / 16) cpa16(KBuf + idx * 16, (const char*)kc0 + idx * 16);
    }
    cpa_commit();

    const int rg0 = q0 + w * 16 + qgrp;      // global row (and rg0+8)
    // ---- Q A-fragments (fp16, scaled) into registers ----
    // m16n8k16 A: reg0={row r,c0,c0+1} reg1={r+8,c0,c0+1} reg2={r,c0+8,+9} reg3={r+8,c0+8,+9}
    uint32_t qA[8][4];
    {
        const float qs = LOG2E_F * 0.08838834764831845f;  // log2e/sqrt(128)
        const float* qb0 = q + (((size_t)b * SQ + rg0) * HQ + h) * DH;
        const float* qb1 = qb0 + (size_t)8 * HQ * DH;
        #pragma unroll
        for (int t = 0; t < 8; ++t) {
            const int c0 = t * 16 + 2 * qid;
            float2 f0 = *(const float2*)(qb0 + c0);
            float2 f1 = *(const float2*)(qb0 + c0 + 8);
            float2 f2 = *(const float2*)(qb1 + c0);
            float2 f3 = *(const float2*)(qb1 + c0 + 8);
            qA[t][0] = packh2(f0.x * qs, f0.y * qs);
            qA[t][1] = packh2(f2.x * qs, f2.y * qs);
            qA[t][2] = packh2(f1.x * qs, f1.y * qs);
            qA[t][3] = packh2(f3.x * qs, f3.y * qs);
        }
    }

    const float* mrow0 = mask + ((size_t)(b * HQ + h) * SQ + rg0) * SKV;
    const float* mrow1 = mrow0 + (size_t)8 * SKV;

    float O[16][4];
    #pragma unroll
    for (int nt = 0; nt < 16; ++nt) {
        O[nt][0] = 0.f; O[nt][1] = 0.f; O[nt][2] = 0.f; O[nt][3] = 0.f;
    }
    float ls0 = 0.f, ls1 = 0.f;

    for (int j = 0; j < ntiles; ++j) {
        const int kv0 = j * BC;

        cpa_wait0();                 // K_j resident (only pending group)
        __syncthreads();             // publish K_j; proves MMA2_{j-1} done (V free)

        // ---- issue V_j (hidden under MMA1 + softmax) ----
        {
            const char* vs = (const char*)(vc0 + (size_t)j * (DH * VTSTR_H));
            #pragma unroll
            for (int i = 0; i < 10; ++i) {
                int idx = tid + NT * i;
                if (idx < V_TILE_BYTES / 16) cpa16(VBuf + idx * 16, vs + idx * 16);
            }
        }
        cpa_commit();                // group: V_j

        // ---- mask prefetch into registers (hidden under MMA1) ----
        float2 mk0[8], mk1[8];
        #pragma unroll
        for (int nt = 0; nt < 8; ++nt) {
            mk0[nt] = *(const float2*)(mrow0 + kv0 + nt * 8 + 2 * qid);
            mk1[nt] = *(const float2*)(mrow1 + kv0 + nt * 8 + 2 * qid);
        }

        // ---- MMA1: S(m16 x n64) = Q @ K^T (fp16 k16 steps) ----
        float S[8][4];
        #pragma unroll
        for (int nt = 0; nt < 8; ++nt) {
            S[nt][0] = 0.f; S[nt][1] = 0.f; S[nt][2] = 0.f; S[nt][3] = 0.f;
        }
        #pragma unroll
        for (int t = 0; t < 8; ++t) {            // dh 16-blocks
            #pragma unroll
            for (int nt = 0; nt < 8; ++nt) {     // kv n8-blocks
                uint2 bb = *(const uint2*)(Ks + (nt * 8 + qgrp) * KSTR_H
                                           + t * 16 + 4 * qid);
                mma16(S[nt], qA[t], bb);
            }
        }
        __syncthreads();             // all K_j reads done -> K buffer free

        // ---- issue K_{j+1} (hidden under softmax + MMA2) ----
        if (j + 1 < ntiles) {
            const char* ks = (const char*)(kc0 + (size_t)(j + 1) * (BC * (KSTR_H / 2)));
            #pragma unroll
            for (int i = 0; i < 9; ++i) {
                int idx = tid + NT * i;
                if (idx < K_TILE_BYTES / 16) cpa16(KBuf + idx * 16, ks + idx * 16);
            }
        }
        cpa_commit();                // group: K_{j+1} (possibly empty)

        // ---- softmax: P = exp2(S + mask*log2e), causal-zeroed, in regs ----
        #pragma unroll
        for (int nt = 0; nt < 8; ++nt) {
            const int c0 = kv0 + nt * 8 + 2 * qid;
            float p00 = (c0     <= rg0)     ? ex2f(S[nt][0] + LOG2E_F * mk0[nt].x) : 0.f;
            float p01 = (c0 + 1 <= rg0)     ? ex2f(S[nt][1] + LOG2E_F * mk0[nt].y) : 0.f;
            float p10 = (c0     <= rg0 + 8) ? ex2f(S[nt][2] + LOG2E_F * mk1[nt].x) : 0.f;
            float p11 = (c0 + 1 <= rg0 + 8) ? ex2f(S[nt][3] + LOG2E_F * mk1[nt].y) : 0.f;
            ls0 += p00 + p01;
            ls1 += p10 + p11;
            S[nt][0] = p00; S[nt][1] = p01; S[nt][2] = p10; S[nt][3] = p11;
        }

        cpa_wait1();                 // V_j done (K_{j+1} may still be pending)
        __syncthreads();             // publish V_j

        // ---- MMA2: O(m16 x d128) += P @ V (fp16, P packed from registers) --
        #pragma unroll
        for (int t = 0; t < 4; ++t) {            // kv 16-blocks
            uint32_t pA[4];
            pA[0] = packh2(S[2 * t][0],     S[2 * t][1]);
            pA[1] = packh2(S[2 * t][2],     S[2 * t][3]);
            pA[2] = packh2(S[2 * t + 1][0], S[2 * t + 1][1]);
            pA[3] = packh2(S[2 * t + 1][2], S[2 * t + 1][3]);
            #pragma unroll
            for (int nt = 0; nt < 16; ++nt) {    // d n8-blocks
                uint2 bb = *(const uint2*)(Vs + (nt * 8 + qgrp) * VTSTR_H
                                           + t * 16 + 4 * qid);
                mma16(O[nt], pA, bb);
            }
        }
    }

    // ---- row sums (reduce over qid lanes), normalize, store ----
    ls0 += __shfl_xor_sync(0xffffffffu, ls0, 1);
    ls0 += __shfl_xor_sync(0xffffffffu, ls0, 2);
    ls1 += __shfl_xor_sync(0xffffffffu, ls1, 1);
    ls1 += __shfl_xor_sync(0xffffffffu, ls1, 2);
    const float inv0 = 1.0f / ls0;
    const float inv1 = 1.0f / ls1;

    float* o0 = out + (((size_t)b * SQ + rg0) * HQ + h) * DH;
    float* o1 = o0 + (size_t)8 * HQ * DH;
    #pragma unroll
    for (int nt = 0; nt < 16; ++nt) {
        const int c = nt * 8 + 2 * qid;
        *(float2*)(o0 + c) = make_float2(O[nt][0] * inv0, O[nt][1] * inv0);
        *(float2*)(o1 + c) = make_float2(O[nt][2] * inv1, O[nt][3] * inv1);
    }
}

extern "C" void kernel_launch(void* const* d_in, const int* in_sizes, int n_in,
                              void* d_out, int out_size) {
    (void)in_sizes; (void)n_in; (void)out_size;
    const float* q = (const float*)d_in[0];
    const float* k = (const float*)d_in[1];
    const float* v = (const float*)d_in[2];
    const float* mask = (const float*)d_in[3];
    float* out = (float*)d_out;

    cudaFuncSetAttribute(fa_kernel,
                         cudaFuncAttributeMaxDynamicSharedMemorySize,
                         (int)SMEM_BYTES);

    kprep_kernel<<<(Bz * SKV * HKV * DH / 4) / 256, 256>>>(k);
    vtprep_kernel<<<dim3(NTILE, DH / 32, Bz * HKV), dim3(32, 8)>>>(v);
    fa_kernel<<<dim3(SQ / BR, HQ, Bz), NT, SMEM_BYTES>>>(q, mask, out);
}

// round 16
// speedup vs baseline: 1.9344x; 1.2343x over previous
#include <cuda_runtime.h>
#include <cuda_fp16.h>
#include <cstdint>

#define LOG2E_F 1.44269504088896340736f

constexpr int Bz = 2, SQ = 2048, SKV = 2048, HQ = 16, HKV = 4, DH = 128;
constexpr int BR = 64, BC = 128, NT = 128;
constexpr int NTILE = SKV / BC;              // 16 kv tiles per (b,hk)

// fp16 smem strides (in half units)
constexpr int KSTR_H  = 144;   // K row: 128 halves + pad (72 words mod 32 = 8)
constexpr int VTSTR_H = 144;   // V^T row: 128 halves + pad
constexpr int K_TILE_BYTES = BC * KSTR_H * 2;     // 36864
constexpr int V_TILE_BYTES = DH * VTSTR_H * 2;    // 36864
constexpr size_t SMEM_BYTES = K_TILE_BYTES + V_TILE_BYTES;  // 73728 -> 2 CTAs/SM

// packed K: [b][hk][tile128][kv(128)][144h] fp16, 16-block interleave on dh
__device__ __half2 g_kc[(size_t)Bz * HKV * NTILE * BC * (KSTR_H / 2)];
// packed V^T: [b][hk][tile128][d(128)][144h] fp16, 16-block interleave on kv
__device__ __half g_vtc[(size_t)Bz * HKV * NTILE * DH * VTSTR_H];

// ---------------- helpers ----------------
__device__ __forceinline__ float ex2f(float x) {
    float y;
    asm("ex2.approx.f32 %0, %1;" : "=f"(y) : "f"(x));
    return y;
}
__device__ __forceinline__ uint32_t smem_u32(const void* p) {
    uint32_t a;
    asm("{ .reg .u64 t; cvta.to.shared.u64 t, %1; cvt.u32.u64 %0, t; }"
        : "=r"(a) : "l"(p));
    return a;
}
__device__ __forceinline__ void cpa16(uint32_t dst, const void* src) {
    asm volatile("cp.async.cg.shared.global [%0], [%1], 16;"
                 :: "r"(dst), "l"(src));
}
__device__ __forceinline__ void cpa_commit() {
    asm volatile("cp.async.commit_group;" ::: "memory");
}
__device__ __forceinline__ void cpa_wait0() {
    asm volatile("cp.async.wait_group 0;" ::: "memory");
}
__device__ __forceinline__ void cpa_wait1() {
    asm volatile("cp.async.wait_group 1;" ::: "memory");
}
__device__ __forceinline__ uint32_t packh2(float lo, float hi) {
    __half2 h = __floats2half2_rn(lo, hi);
    return *reinterpret_cast<uint32_t*>(&h);
}
// m16n8k16 row.col fp16 mma, fp32 accumulate
__device__ __forceinline__ void mma16(float* c, const uint32_t* a, uint2 b) {
    asm volatile(
        "mma.sync.aligned.m16n8k16.row.col.f32.f16.f16.f32 "
        "{%0,%1,%2,%3}, {%4,%5,%6,%7}, {%8,%9}, {%0,%1,%2,%3};\n"
        : "+f"(c[0]), "+f"(c[1]), "+f"(c[2]), "+f"(c[3])
        : "r"(a[0]), "r"(a[1]), "r"(a[2]), "r"(a[3]), "r"(b.x), "r"(b.y));
}
// 16-block interleave: pos(k) = 4*((k>>1)&3) + (k&1) + 2*((k>>3)&1) within block
// -> B-fragment {k=2q, 2q+1, 2q+8, 2q+9} is one aligned LDS.64 at half-offset 4q
__device__ __forceinline__ int vperm16(int k) {
    return (k & ~15) + 4 * ((k >> 1) & 3) + (k & 1) + 2 * ((k >> 3) & 1);
}

// ---------------- prepass: K pack (fp16, 16-block interleave on dh) --------
__global__ void kprep_kernel(const float* __restrict__ k) {
    int idx = blockIdx.x * 256 + threadIdx.x;     // one float4 each
    int d  = (idx & 31) * 4;
    int t  = idx >> 5;
    int hk = t & 3;  t >>= 2;
    int s  = t & (SKV - 1);
    int b  = t >> 11;
    float4 v4 = *(const float4*)(k + (((size_t)b * SKV + s) * HKV + hk) * DH + d);
    __half2* dst = g_kc + (((size_t)(b * HKV + hk) * NTILE + (s >> 7)) * BC
                           + (s & 127)) * (KSTR_H / 2) + (d & ~15) / 2;
    // h2 slot for (d..d+3): c=(d>>2)&3 -> base {0,4,1,5}, pair +2
    const int c = (d >> 2) & 3;
    int a0 = (c == 0) ? 0 : (c == 1) ? 4 : (c == 2) ? 1 : 5;
    dst[a0]     = __floats2half2_rn(v4.x, v4.y);
    dst[a0 + 2] = __floats2half2_rn(v4.z, v4.w);
}

// ---------------- prepass: V transpose+pack (fp16, interleave on kv) -------
__global__ void vtprep_kernel(const float* __restrict__ v) {
    __shared__ float t[64][33];
    const int kvt = blockIdx.x;          // kv sub-tile (64 wide)
    const int d0  = blockIdx.y * 32;
    const int bh  = blockIdx.z;          // b*HKV+hk
    const int b = bh >> 2, hk = bh & 3;
    const int tx = threadIdx.x, ty = threadIdx.y;   // 32 x 8
    const float* src = v + ((size_t)b * SKV * HKV + hk) * DH + d0;
    #pragma unroll
    for (int i = 0; i < 8; ++i) {
        int kvl = ty + 8 * i;
        t[kvl][tx] = src[(size_t)(kvt * 64 + kvl) * (HKV * DH) + tx];
    }
    __syncthreads();
    __half* dst = g_vtc + ((size_t)bh * NTILE + (kvt >> 1)) * (DH * VTSTR_H)
                + (size_t)d0 * VTSTR_H;
    const int kvbase = (kvt & 1) * 64;
    #pragma unroll
    for (int i = 0; i < 8; ++i) {
        int e = i * 256 + ty * 32 + tx;
        int dl = e >> 6, kvl = e & 63;
        dst[dl * VTSTR_H + vperm16(kvbase + kvl)] = __float2half_rn(t[kvl][dl]);
    }
}

// ---------------- main attention kernel ----------------
__global__ void __launch_bounds__(NT, 2)
fa_kernel(const float* __restrict__ q,
          const float* __restrict__ mask,
          float* __restrict__ out)
{
    extern __shared__ char sma[];
    __half* Ks = (__half*)sma;
    __half* Vs = (__half*)(sma + K_TILE_BYTES);
    const uint32_t KBuf = smem_u32(Ks);
    const uint32_t VBuf = smem_u32(Vs);

    const int tid = threadIdx.x;
    const int w = tid >> 5;            // 4 warps, warp owns rows w*16..w*16+15
    const int lane = tid & 31;
    const int qgrp = lane >> 2;
    const int qid  = lane & 3;

    const int bx = blockIdx.x;
    const int q0 = bx * BR;
    const int h  = blockIdx.y;
    const int b  = blockIdx.z;
    const int hk = h & (HKV - 1);
    const int bh = b * HKV + hk;
    const int ntiles = (64 * bx + 191) >> 7;   // 128-wide tiles covering causal range

    const __half2* kc0 = g_kc + (size_t)bh * NTILE * (BC * (KSTR_H / 2));
    const __half*  vc0 = g_vtc + (size_t)bh * NTILE * (DH * VTSTR_H);

    // ---- prologue: issue K_0 (group) ----
    #pragma unroll
    for (int i = 0; i < 18; ++i) {
        int idx = tid + NT * i;
        cpa16(KBuf + idx * 16, (const char*)kc0 + idx * 16);
    }
    cpa_commit();

    const int rg0 = q0 + w * 16 + qgrp;      // global row (and rg0+8)
    const int rwmax = q0 + w * 16 + 15;      // causal warp bound

    // ---- Q A-fragments (fp16, scaled) into registers ----
    uint32_t qA[8][4];
    {
        const float qs = LOG2E_F * 0.08838834764831845f;  // log2e/sqrt(128)
        const float* qb0 = q + (((size_t)b * SQ + rg0) * HQ + h) * DH;
        const float* qb1 = qb0 + (size_t)8 * HQ * DH;
        #pragma unroll
        for (int t = 0; t < 8; ++t) {
            const int c0 = t * 16 + 2 * qid;
            float2 f0 = *(const float2*)(qb0 + c0);
            float2 f1 = *(const float2*)(qb0 + c0 + 8);
            float2 f2 = *(const float2*)(qb1 + c0);
            float2 f3 = *(const float2*)(qb1 + c0 + 8);
            qA[t][0] = packh2(f0.x * qs, f0.y * qs);
            qA[t][1] = packh2(f2.x * qs, f2.y * qs);
            qA[t][2] = packh2(f1.x * qs, f1.y * qs);
            qA[t][3] = packh2(f3.x * qs, f3.y * qs);
        }
    }

    const float* mrow0 = mask + ((size_t)(b * HQ + h) * SQ + rg0) * SKV;
    const float* mrow1 = mrow0 + (size_t)8 * SKV;

    float O[16][4];
    #pragma unroll
    for (int nt = 0; nt < 16; ++nt) {
        O[nt][0] = 0.f; O[nt][1] = 0.f; O[nt][2] = 0.f; O[nt][3] = 0.f;
    }
    float ls0 = 0.f, ls1 = 0.f;

    for (int j = 0; j < ntiles; ++j) {
        const int kv0 = j * BC;

        cpa_wait0();                 // K_j resident (only real pending group)
        __syncthreads();             // publish K_j; proves MMA2_{j-1} done (V free)

        // ---- issue V_j (hidden under MMA1 both halves + softmax) ----
        {
            const char* vs = (const char*)(vc0 + (size_t)j * (DH * VTSTR_H));
            #pragma unroll
            for (int i = 0; i < 18; ++i) {
                int idx = tid + NT * i;
                cpa16(VBuf + idx * 16, vs + idx * 16);
            }
        }
        cpa_commit();                // group: V_j

        // ---- S = Q@K^T + softmax, processed in two 64-kv halves ----
        float S[16][4];
        #pragma unroll
        for (int half = 0; half < 2; ++half) {
            const int kvh = kv0 + half * 64;
            float* Sh0 = &S[half * 8][0];
            if (kvh <= rwmax) {
                // mask prefetch for this half (hidden under its MMA1)
                float2 mk0[8], mk1[8];
                #pragma unroll
                for (int nt = 0; nt < 8; ++nt) {
                    mk0[nt] = *(const float2*)(mrow0 + kvh + nt * 8 + 2 * qid);
                    mk1[nt] = *(const float2*)(mrow1 + kvh + nt * 8 + 2 * qid);
                }
                #pragma unroll
                for (int nt = 0; nt < 8; ++nt) {
                    Sh0[nt * 4 + 0] = 0.f; Sh0[nt * 4 + 1] = 0.f;
                    Sh0[nt * 4 + 2] = 0.f; Sh0[nt * 4 + 3] = 0.f;
                }
                #pragma unroll
                for (int t = 0; t < 8; ++t) {            // dh 16-blocks
                    #pragma unroll
                    for (int nt = 0; nt < 8; ++nt) {     // kv n8-blocks
                        uint2 bb = *(const uint2*)(Ks + (half * 64 + nt * 8 + qgrp) * KSTR_H
                                                   + t * 16 + 4 * qid);
                        mma16(&Sh0[nt * 4], qA[t], bb);
                    }
                }
                // softmax for this half
                #pragma unroll
                for (int nt = 0; nt < 8; ++nt) {
                    const int c0 = kvh + nt * 8 + 2 * qid;
                    float p00 = (c0     <= rg0)     ? ex2f(Sh0[nt*4+0] + LOG2E_F * mk0[nt].x) : 0.f;
                    float p01 = (c0 + 1 <= rg0)     ? ex2f(Sh0[nt*4+1] + LOG2E_F * mk0[nt].y) : 0.f;
                    float p10 = (c0     <= rg0 + 8) ? ex2f(Sh0[nt*4+2] + LOG2E_F * mk1[nt].x) : 0.f;
                    float p11 = (c0 + 1 <= rg0 + 8) ? ex2f(Sh0[nt*4+3] + LOG2E_F * mk1[nt].y) : 0.f;
                    ls0 += p00 + p01;
                    ls1 += p10 + p11;
                    Sh0[nt*4+0] = p00; Sh0[nt*4+1] = p01;
                    Sh0[nt*4+2] = p10; Sh0[nt*4+3] = p11;
                }
            } else {
                #pragma unroll
                for (int nt = 0; nt < 8; ++nt) {
                    Sh0[nt * 4 + 0] = 0.f; Sh0[nt * 4 + 1] = 0.f;
                    Sh0[nt * 4 + 2] = 0.f; Sh0[nt * 4 + 3] = 0.f;
                }
            }
        }
        __syncthreads();             // all K_j reads done -> K buffer free

        // ---- issue K_{j+1} (hidden under V wait slack + MMA2) ----
        if (j + 1 < ntiles) {
            const char* ks = (const char*)(kc0 + (size_t)(j + 1) * (BC * (KSTR_H / 2)));
            #pragma unroll
            for (int i = 0; i < 18; ++i) {
                int idx = tid + NT * i;
                cpa16(KBuf + idx * 16, ks + idx * 16);
            }
        }
        cpa_commit();                // group: K_{j+1} (possibly empty)

        cpa_wait1();                 // V_j done (K_{j+1} may still be pending)
        __syncthreads();             // publish V_j

        // ---- MMA2: O(m16 x d128) += P @ V over 128 kv (causally guarded) ---
        #pragma unroll
        for (int t = 0; t < 8; ++t) {            // kv 16-blocks
            if (kv0 + t * 16 <= rwmax) {         // warp-uniform guard
                uint32_t pA[4];
                pA[0] = packh2(S[2 * t][0],     S[2 * t][1]);
                pA[1] = packh2(S[2 * t][2],     S[2 * t][3]);
                pA[2] = packh2(S[2 * t + 1][0], S[2 * t + 1][1]);
                pA[3] = packh2(S[2 * t + 1][2], S[2 * t + 1][3]);
                #pragma unroll
                for (int nt = 0; nt < 16; ++nt) {    // d n8-blocks
                    uint2 bb = *(const uint2*)(Vs + (nt * 8 + qgrp) * VTSTR_H
                                               + t * 16 + 4 * qid);
                    mma16(O[nt], pA, bb);
                }
            }
        }
    }

    // ---- row sums (reduce over qid lanes), normalize, store ----
    ls0 += __shfl_xor_sync(0xffffffffu, ls0, 1);
    ls0 += __shfl_xor_sync(0xffffffffu, ls0, 2);
    ls1 += __shfl_xor_sync(0xffffffffu, ls1, 1);
    ls1 += __shfl_xor_sync(0xffffffffu, ls1, 2);
    const float inv0 = 1.0f / ls0;
    const float inv1 = 1.0f / ls1;

    float* o0 = out + (((size_t)b * SQ + rg0) * HQ + h) * DH;
    float* o1 = o0 + (size_t)8 * HQ * DH;
    #pragma unroll
    for (int nt = 0; nt < 16; ++nt) {
        const int c = nt * 8 + 2 * qid;
        *(float2*)(o0 + c) = make_float2(O[nt][0] * inv0, O[nt][1] * inv0);
        *(float2*)(o1 + c) = make_float2(O[nt][2] * inv1, O[nt][3] * inv1);
    }
}

extern "C" void kernel_launch(void* const* d_in, const int* in_sizes, int n_in,
                              void* d_out, int out_size) {
    (void)in_sizes; (void)n_in; (void)out_size;
    const float* q = (const float*)d_in[0];
    const float* k = (const float*)d_in[1];
    const float* v = (const float*)d_in[2];
    const float* mask = (const float*)d_in[3];
    float* out = (float*)d_out;

    cudaFuncSetAttribute(fa_kernel,
                         cudaFuncAttributeMaxDynamicSharedMemorySize,
                         (int)SMEM_BYTES);

    kprep_kernel<<<(Bz * SKV * HKV * DH / 4) / 256, 256>>>(k);
    vtprep_kernel<<<dim3(SKV / 64, DH / 32, Bz * HKV), dim3(32, 8)>>>(v);
    fa_kernel<<<dim3(SQ / BR, HQ, Bz), NT, SMEM_BYTES>>>(q, mask, out);
}